// round 3
// baseline (speedup 1.0000x reference)
#include <cuda_runtime.h>
#include <math.h>

#define BB 128
#define CC 320
#define NP 256
#define GRP 5
#define HID 40
#define PADW 18
#define NB 3

static __device__ __align__(16) float g_avg[BB*CC];
static __device__ __align__(16) float g_cw[BB*NB*CC];
static __device__ __align__(16) float g_mker[NB*NP];
static __device__ __align__(16) float g_wt[(size_t)NB*9*CC*CC];
static __device__ __align__(16) float g_bandpad[(size_t)NB*BB*PADW*PADW*CC];
static __device__ __align__(16) float g_conv[(size_t)NB*BB*NP*CC];
static __device__ __align__(16) float g_xT[(size_t)BB*NP*CC];
static __device__ __align__(16) float g_fused[(size_t)BB*NP*CC];
static __device__ float g_swl[BB*NP];
static __device__ float g_mu[NB*BB*GRP];
static __device__ float g_rs[NB*BB*GRP];

// ---------------- channel means over N -----------------------------------
__global__ void k_avg(const float* __restrict__ x){
    int row  = blockIdx.x*8 + (threadIdx.x>>5);
    int lane = threadIdx.x & 31;
    if(row >= BB*CC) return;
    const float* p = x + (size_t)row*NP;
    float s = 0.f;
    for(int k=lane;k<NP;k+=32) s += p[k];
    #pragma unroll
    for(int o=16;o;o>>=1) s += __shfl_xor_sync(0xffffffffu, s, o);
    if(!lane) g_avg[row] = s * (1.0f/NP);
}

// ---------------- channel attention (tiny MLP) ---------------------------
__global__ void k_ca(const float* __restrict__ w1, const float* __restrict__ b1,
                     const float* __restrict__ w2, const float* __restrict__ b2){
    __shared__ float av[CC];
    __shared__ float hid[HID];
    int b = blockIdx.x, t = threadIdx.x;
    for(int c=t;c<CC;c+=256) av[c] = g_avg[b*CC+c];
    __syncthreads();
    if(t < HID){
        float s = b1[t];
        const float* wr = w1 + t*CC;
        for(int c=0;c<CC;c++) s += av[c]*wr[c];
        hid[t] = fmaxf(s, 0.f);
    }
    __syncthreads();
    for(int j=t;j<NB*CC;j+=256){
        float s = b2[j];
        const float* wr = w2 + j*HID;
        #pragma unroll
        for(int i=0;i<HID;i++) s += hid[i]*wr[i];
        g_cw[b*NB*CC + j] = 1.f/(1.f + expf(-s));
    }
}

// ---------------- masks -> real circular-conv kernels --------------------
__device__ __forceinline__ double dsig(float a){ return 1.0/(1.0 + exp(-(double)a)); }

__global__ void k_mker(const float* __restrict__ lcp, const float* __restrict__ hcp){
    __shared__ float msk[NB*NP];
    __shared__ double ct[16];
    int t = threadIdx.x;      // 256
    if(t < 16) ct[t] = cos(6.283185307179586 * (double)t / 16.0);
    float lc = *lcp, hc = *hcp;
    {
        int i = t>>4, j = t&15;
        const float step = 0.13333334f;   // fp32(2/15), matches jnp.linspace
        float yy = __fadd_rn(-1.0f, __fmul_rn((float)i, step));
        float xx = __fadd_rn(-1.0f, __fmul_rn((float)j, step));
        float d2 = __fadd_rn(__fmul_rn(xx,xx), __fmul_rn(yy,yy));
        float dist = __fdiv_rn(__fsqrt_rn(d2), 1.41421356f);
        float a_l  = __fdiv_rn(__fsub_rn(lc, dist), 1e-6f);
        float a_m1 = __fdiv_rn(__fsub_rn(dist, lc), 1e-6f);
        float a_m2 = __fdiv_rn(__fsub_rn(hc, dist), 1e-6f);
        float a_h  = __fdiv_rn(__fsub_rn(dist, hc), 1e-6f);
        msk[0*NP + t] = (float)dsig(a_l);
        msk[1*NP + t] = (float)(dsig(a_m1)*dsig(a_m2));
        msk[2*NP + t] = (float)dsig(a_h);
    }
    __syncthreads();
    int ph = t>>4, pw = t&15;
    for(int s=0;s<NB;s++){
        double acc = 0.0;
        for(int u=0;u<16;u++)
            for(int v=0;v<16;v++){
                float mv = msk[s*NP + ((((u+8)&15)<<4) | ((v+8)&15))];
                acc += (double)mv * ct[(u*ph + v*pw)&15];
            }
        g_mker[s*NP + t] = (float)(acc/256.0);
    }
}

// ---------------- transpose x to [b][p][c] -------------------------------
__global__ void k_xt(const float* __restrict__ x){
    __shared__ float sm[32][33];
    int b = blockIdx.z, c0 = blockIdx.y*32, p0 = blockIdx.x*32;
    int tx = threadIdx.x, ty = threadIdx.y;
    sm[ty][tx] = x[((size_t)b*CC + c0+ty)*NP + p0+tx];
    __syncthreads();
    g_xT[((size_t)b*NP + p0+ty)*CC + c0+tx] = sm[tx][ty];
}

// ---------------- weights -> [s][tap][c][o] ------------------------------
__global__ void k_wt(const float* __restrict__ lw, const float* __restrict__ mw,
                     const float* __restrict__ hw){
    size_t idx = (size_t)blockIdx.x*256 + threadIdx.x;
    const size_t tot = (size_t)NB*9*CC*CC;
    if(idx >= tot) return;
    int o   = (int)(idx % CC);
    int c   = (int)((idx/CC) % CC);
    int tap = (int)((idx/((size_t)CC*CC)) % 9);
    int s   = (int)(idx/((size_t)9*CC*CC));
    const float* w = (s==0) ? lw : ((s==1) ? mw : hw);
    g_wt[idx] = w[(size_t)o*CC*9 + (size_t)c*9 + tap];
}

// ---------------- zero the padded border ---------------------------------
__global__ void k_zero(){
    int idx = blockIdx.x*256 + threadIdx.x;
    const int tot = NB*BB*68*80;
    if(idx >= tot) return;
    int q  = idx % 80;
    int bi = (idx/80) % 68;
    int pl = idx/(80*68);
    int r, cn;
    if(bi < 18){ r = 0;  cn = bi; }
    else if(bi < 36){ r = 17; cn = bi-18; }
    else { int k = bi-36; r = 1 + (k>>1); cn = (k&1) ? 17 : 0; }
    ((float4*)g_bandpad)[ (((size_t)pl*PADW + r)*PADW + cn)*80 + q ] =
        make_float4(0.f,0.f,0.f,0.f);
}

// ---------------- band filtering via 2D circular conv --------------------
__global__ void __launch_bounds__(256) k_band(const float* __restrict__ x){
    __shared__ float Xs[NP][36];     // [q][c-in-tile]
    __shared__ float ms[NB*NP];
    int b = blockIdx.y, c0 = blockIdx.x*32, t = threadIdx.x;
    for(int i=t;i<NB*NP;i+=256) ms[i] = g_mker[i];
    const float* xb = x + ((size_t)b*CC + c0)*NP;
    for(int i=t;i<2048;i+=256){
        int cl = i>>6, q4 = (i&63)<<2;
        float4 v = *(const float4*)(xb + (size_t)cl*NP + q4);
        Xs[q4+0][cl]=v.x; Xs[q4+1][cl]=v.y; Xs[q4+2][cl]=v.z; Xs[q4+3][cl]=v.w;
    }
    __syncthreads();
    int cg = t&1, pg = t>>1;
    int pA = pg*2, pB = pg*2+1;
    int phA = pA>>4, pwA = pA&15, phB = pB>>4, pwB = pB&15;
    for(int s=0;s<NB;s++){
        const float* msp = ms + s*NP;
        float a0[16], a1[16];
        #pragma unroll
        for(int j=0;j<16;j++){ a0[j]=0.f; a1[j]=0.f; }
        for(int q=0;q<NP;q++){
            int qh=q>>4, qw=q&15;
            float m0 = msp[(((phA-qh)&15)<<4) | ((pwA-qw)&15)];
            float m1 = msp[(((phB-qh)&15)<<4) | ((pwB-qw)&15)];
            const float* xr = &Xs[q][cg*16];
            float4 v0 = *(const float4*)(xr+0);
            float4 v1 = *(const float4*)(xr+4);
            float4 v2 = *(const float4*)(xr+8);
            float4 v3 = *(const float4*)(xr+12);
            a0[0]+=m0*v0.x; a0[1]+=m0*v0.y; a0[2]+=m0*v0.z; a0[3]+=m0*v0.w;
            a0[4]+=m0*v1.x; a0[5]+=m0*v1.y; a0[6]+=m0*v1.z; a0[7]+=m0*v1.w;
            a0[8]+=m0*v2.x; a0[9]+=m0*v2.y; a0[10]+=m0*v2.z; a0[11]+=m0*v2.w;
            a0[12]+=m0*v3.x; a0[13]+=m0*v3.y; a0[14]+=m0*v3.z; a0[15]+=m0*v3.w;
            a1[0]+=m1*v0.x; a1[1]+=m1*v0.y; a1[2]+=m1*v0.z; a1[3]+=m1*v0.w;
            a1[4]+=m1*v1.x; a1[5]+=m1*v1.y; a1[6]+=m1*v1.z; a1[7]+=m1*v1.w;
            a1[8]+=m1*v2.x; a1[9]+=m1*v2.y; a1[10]+=m1*v2.z; a1[11]+=m1*v2.w;
            a1[12]+=m1*v3.x; a1[13]+=m1*v3.y; a1[14]+=m1*v3.z; a1[15]+=m1*v3.w;
        }
        {
            int h = phA+1, w = pwA+1;
            float* dst = g_bandpad + (((size_t)(s*BB+b)*PADW + h)*PADW + w)*CC + c0 + cg*16;
            *(float4*)(dst+0)  = make_float4(a0[0],a0[1],a0[2],a0[3]);
            *(float4*)(dst+4)  = make_float4(a0[4],a0[5],a0[6],a0[7]);
            *(float4*)(dst+8)  = make_float4(a0[8],a0[9],a0[10],a0[11]);
            *(float4*)(dst+12) = make_float4(a0[12],a0[13],a0[14],a0[15]);
        }
        {
            int h = phB+1, w = pwB+1;
            float* dst = g_bandpad + (((size_t)(s*BB+b)*PADW + h)*PADW + w)*CC + c0 + cg*16;
            *(float4*)(dst+0)  = make_float4(a1[0],a1[1],a1[2],a1[3]);
            *(float4*)(dst+4)  = make_float4(a1[4],a1[5],a1[6],a1[7]);
            *(float4*)(dst+8)  = make_float4(a1[8],a1[9],a1[10],a1[11]);
            *(float4*)(dst+12) = make_float4(a1[12],a1[13],a1[14],a1[15]);
        }
    }
}

// ---------------- 3x3 conv as implicit GEMM ------------------------------
__global__ void __launch_bounds__(256) k_conv(const float* __restrict__ lb,
                                              const float* __restrict__ mb,
                                              const float* __restrict__ hb){
    __shared__ float As[16][132];   // [c][pixel-row]
    __shared__ float Bs[16][64];    // [c][outch]
    int s = blockIdx.z, mt = blockIdx.y, nt = blockIdx.x;
    int b = mt>>1, p0 = (mt&1)<<7, n0 = nt*64;
    int t = threadIdx.x, tn = t&15, tm = t>>4;
    const float* bias  = (s==0) ? lb : ((s==1) ? mb : hb);
    const float* wbase = g_wt + (size_t)s*9*CC*CC;
    const float* bp    = g_bandpad + (size_t)(s*BB+b)*PADW*PADW*CC;
    float acc[8][4];
    #pragma unroll
    for(int i=0;i<8;i++){ acc[i][0]=0.f; acc[i][1]=0.f; acc[i][2]=0.f; acc[i][3]=0.f; }

    for(int dy=0;dy<3;dy++)
    for(int dx=0;dx<3;dx++){
        const float* wtap = wbase + (size_t)(dy*3+dx)*CC*CC + n0;
        for(int kc=0;kc<CC;kc+=16){
            __syncthreads();
            #pragma unroll
            for(int k=0;k<2;k++){
                int idx = t + k*256;
                int r = idx>>2, cp = idx&3;
                int p = p0 + r, h = p>>4, w = p&15;
                float4 v = *(const float4*)(bp + ((size_t)(h+dy)*PADW + (w+dx))*CC + kc + cp*4);
                As[cp*4+0][r]=v.x; As[cp*4+1][r]=v.y; As[cp*4+2][r]=v.z; As[cp*4+3][r]=v.w;
            }
            {
                int cl = t>>4, nf = (t&15)<<2;
                *(float4*)&Bs[cl][nf] = *(const float4*)(wtap + (size_t)(kc+cl)*CC + nf);
            }
            __syncthreads();
            #pragma unroll
            for(int kk=0;kk<16;kk++){
                float4 x0 = *(const float4*)&As[kk][tm*8];
                float4 x1 = *(const float4*)&As[kk][tm*8+4];
                float4 bv = *(const float4*)&Bs[kk][tn*4];
                float a[8] = {x0.x,x0.y,x0.z,x0.w,x1.x,x1.y,x1.z,x1.w};
                #pragma unroll
                for(int i=0;i<8;i++){
                    acc[i][0]+=a[i]*bv.x; acc[i][1]+=a[i]*bv.y;
                    acc[i][2]+=a[i]*bv.z; acc[i][3]+=a[i]*bv.w;
                }
            }
        }
    }
    float4 bz = *(const float4*)(bias + n0 + tn*4);
    #pragma unroll
    for(int i=0;i<8;i++){
        int p = p0 + tm*8 + i;
        float4 o = make_float4(acc[i][0]+bz.x, acc[i][1]+bz.y, acc[i][2]+bz.z, acc[i][3]+bz.w);
        *(float4*)(g_conv + ((size_t)(s*BB+b)*NP + p)*CC + n0 + tn*4) = o;
    }
}

// ---------------- group-norm statistics ----------------------------------
__global__ void k_gn(){
    __shared__ float rs[8], rq[8];
    int g = blockIdx.x, b = blockIdx.y, s = blockIdx.z;
    int t = threadIdx.x;
    const float* base = g_conv + (size_t)(s*BB+b)*NP*CC + g*64;
    float sm = 0.f, sq = 0.f;
    for(int i=t;i<16384;i+=256){
        int p = i>>6, c = i&63;
        float v = base[(size_t)p*CC + c];
        sm += v; sq += v*v;
    }
    #pragma unroll
    for(int o=16;o;o>>=1){ sm += __shfl_xor_sync(0xffffffffu, sm, o);
                           sq += __shfl_xor_sync(0xffffffffu, sq, o); }
    if(!(t&31)){ rs[t>>5]=sm; rq[t>>5]=sq; }
    __syncthreads();
    if(t==0){
        float S=0.f, Q=0.f;
        for(int i=0;i<8;i++){ S+=rs[i]; Q+=rq[i]; }
        float mu = S*(1.0f/16384.0f);
        float var = Q*(1.0f/16384.0f) - mu*mu;
        int o = (s*BB+b)*GRP + g;
        g_mu[o] = mu;
        g_rs[o] = rsqrtf(var + 1e-5f);
    }
}

// ---------------- fuse: GN affine + residual + cw mix + SA logit ---------
__global__ void k_fuse1(const float* __restrict__ lg, const float* __restrict__ lbeta,
                        const float* __restrict__ mg, const float* __restrict__ mbeta,
                        const float* __restrict__ hg, const float* __restrict__ hbeta,
                        const float* __restrict__ saw){
    __shared__ float red[10];
    int p = blockIdx.x, b = blockIdx.y, c = threadIdx.x;
    int g = c>>6;
    float xv = g_xT[((size_t)b*NP+p)*CC + c];
    float fused = 0.f;
    #pragma unroll
    for(int s=0;s<NB;s++){
        const float* gam = (s==0)?lg:((s==1)?mg:hg);
        const float* bet = (s==0)?lbeta:((s==1)?mbeta:hbeta);
        float v  = g_conv[((size_t)(s*BB+b)*NP+p)*CC + c];
        float mu = g_mu[(s*BB+b)*GRP+g];
        float rr = g_rs[(s*BB+b)*GRP+g];
        float feat = (v-mu)*rr*gam[c] + bet[c] + xv;
        fused += g_cw[(size_t)b*NB*CC + s*CC + c] * feat;
    }
    g_fused[((size_t)b*NP+p)*CC + c] = fused;
    float part = fused * saw[c];
    #pragma unroll
    for(int o=16;o;o>>=1) part += __shfl_xor_sync(0xffffffffu, part, o);
    if(!(c&31)) red[c>>5] = part;
    __syncthreads();
    if(c==0){
        float S=0.f;
        for(int i=0;i<10;i++) S += red[i];
        g_swl[b*NP+p] = S;
    }
}

// ---------------- apply SA and transpose back to [b][c][p] ---------------
__global__ void k_fuse2(const float* __restrict__ sab, float* __restrict__ out){
    __shared__ float sm[32][33];
    __shared__ float sws[32];
    int b = blockIdx.z, c0 = blockIdx.y*32, p0 = blockIdx.x*32;
    int tx = threadIdx.x, ty = threadIdx.y;
    sm[ty][tx] = g_fused[((size_t)b*NP + p0+ty)*CC + c0+tx];
    if(ty==0) sws[tx] = 1.f/(1.f + expf(-(g_swl[b*NP + p0+tx] + sab[0])));
    __syncthreads();
    out[((size_t)b*CC + c0+ty)*NP + p0+tx] = sm[tx][ty]*sws[tx];
}

extern "C" void kernel_launch(void* const* d_in, const int* in_sizes, int n_in,
                              void* d_out, int out_size){
    const float* x   = (const float*)d_in[0];
    const float* lcp = (const float*)d_in[1];
    const float* hcp = (const float*)d_in[2];
    const float* w1  = (const float*)d_in[3];
    const float* b1  = (const float*)d_in[4];
    const float* w2  = (const float*)d_in[5];
    const float* b2  = (const float*)d_in[6];
    const float* lw  = (const float*)d_in[7];
    const float* lb  = (const float*)d_in[8];
    const float* lg  = (const float*)d_in[9];
    const float* lbe = (const float*)d_in[10];
    const float* mw  = (const float*)d_in[11];
    const float* mb  = (const float*)d_in[12];
    const float* mg  = (const float*)d_in[13];
    const float* mbe = (const float*)d_in[14];
    const float* hw  = (const float*)d_in[15];
    const float* hb  = (const float*)d_in[16];
    const float* hg  = (const float*)d_in[17];
    const float* hbe = (const float*)d_in[18];
    const float* saw = (const float*)d_in[19];
    const float* sab = (const float*)d_in[20];
    float* out = (float*)d_out;

    k_avg <<<(BB*CC+7)/8, 256>>>(x);
    k_ca  <<<BB, 256>>>(w1,b1,w2,b2);
    k_mker<<<1, 256>>>(lcp,hcp);
    k_xt  <<<dim3(8,10,BB), dim3(32,32)>>>(x);
    k_wt  <<<(int)(((size_t)NB*9*CC*CC + 255)/256), 256>>>(lw,mw,hw);
    k_zero<<<(NB*BB*68*80 + 255)/256, 256>>>();
    k_band<<<dim3(10,BB), 256>>>(x);
    k_conv<<<dim3(5,256,3), 256>>>(lb,mb,hb);
    k_gn  <<<dim3(GRP,BB,NB), 256>>>();
    k_fuse1<<<dim3(NP,BB), 320>>>(lg,lbe,mg,mbe,hg,hbe,saw);
    k_fuse2<<<dim3(8,10,BB), dim3(32,32)>>>(sab,out);
}

// round 7
// speedup vs baseline: 1.8359x; 1.8359x over previous
#include <cuda_runtime.h>
#include <cuda_bf16.h>
#include <math.h>
#include <stdint.h>

#define BB 128
#define CC 320
#define NP 256
#define GRP 5
#define HID 40
#define NB 3
#define KTOT 2880          // 9*320

// ---------------- scratch ------------------------------------------------
static __device__ __align__(16) float g_avg[BB*CC];
static __device__ __align__(16) float g_cw[BB*NB*CC];
static __device__ __align__(16) float g_mker[NB*NP];
static __device__ __align__(16) __nv_bfloat16 g_wb[(size_t)NB*2*CC*KTOT];
static __device__ __align__(16) __nv_bfloat16 g_bphi[(size_t)NB*BB*18*18*CC];
static __device__ __align__(16) __nv_bfloat16 g_bplo[(size_t)NB*BB*18*18*CC];
static __device__ __align__(16) float g_conv[(size_t)NB*BB*NP*CC];
static __device__ __align__(16) float g_xT[(size_t)BB*NP*CC];
static __device__ __align__(16) float g_fused[(size_t)BB*NP*CC];
static __device__ float g_swl[BB*NP];
static __device__ float g_mu[NB*BB*GRP];
static __device__ float g_rs[NB*BB*GRP];

// ---------------- helpers ------------------------------------------------
__device__ __forceinline__ uint32_t smem_u32(const void* p){
    uint32_t a;
    asm("{ .reg .u64 t; cvta.to.shared.u64 t, %1; cvt.u32.u64 %0, t; }" : "=r"(a) : "l"(p));
    return a;
}
#define SWZ(x) ((x) ^ (((x)>>3)&0x70))

#define CP_ASYNC16(dst, src) \
    asm volatile("cp.async.cg.shared.global [%0], [%1], 16;" :: "r"(dst), "l"(src))
#define CP_COMMIT()  asm volatile("cp.async.commit_group;")
#define CP_WAIT1()   asm volatile("cp.async.wait_group 1;")
#define CP_WAIT0()   asm volatile("cp.async.wait_group 0;")

#define LDMX4(r0,r1,r2,r3,a) \
    asm volatile("ldmatrix.sync.aligned.m8n8.x4.shared.b16 {%0,%1,%2,%3}, [%4];" \
        : "=r"(r0),"=r"(r1),"=r"(r2),"=r"(r3) : "r"(a))
#define LDMX2(r0,r1,a) \
    asm volatile("ldmatrix.sync.aligned.m8n8.x2.shared.b16 {%0,%1}, [%2];" \
        : "=r"(r0),"=r"(r1) : "r"(a))
#define MMA16816(c0,c1,c2,c3,a0,a1,a2,a3,b0,b1) \
    asm volatile("mma.sync.aligned.m16n8k16.row.col.f32.bf16.bf16.f32 " \
        "{%0,%1,%2,%3}, {%4,%5,%6,%7}, {%8,%9}, {%0,%1,%2,%3};" \
        : "+f"(c0),"+f"(c1),"+f"(c2),"+f"(c3) \
        : "r"(a0),"r"(a1),"r"(a2),"r"(a3),"r"(b0),"r"(b1))

// SMEM stages for conv kernel
#define ASTAGE 16384           // 128 rows x 128B
#define BSTAGE 20480           // 160 rows x 128B
#define STAGE  (ASTAGE+BSTAGE) // 36864
#define SMEM_CONV (2*STAGE)    // 73728

// ---------------- channel means ------------------------------------------
__global__ void k_avg(const float* __restrict__ x){
    int row  = blockIdx.x*8 + (threadIdx.x>>5);
    int lane = threadIdx.x & 31;
    if(row >= BB*CC) return;
    const float* p = x + (size_t)row*NP;
    float s = 0.f;
    for(int k=lane;k<NP;k+=32) s += p[k];
    #pragma unroll
    for(int o=16;o;o>>=1) s += __shfl_xor_sync(0xffffffffu, s, o);
    if(!lane) g_avg[row] = s * (1.0f/NP);
}

// ---------------- channel attention --------------------------------------
__global__ void k_ca(const float* __restrict__ w1, const float* __restrict__ b1,
                     const float* __restrict__ w2, const float* __restrict__ b2){
    __shared__ float av[CC];
    __shared__ float hid[HID];
    int b = blockIdx.x, t = threadIdx.x;
    for(int c=t;c<CC;c+=256) av[c] = g_avg[b*CC+c];
    __syncthreads();
    if(t < HID){
        float s = b1[t];
        const float* wr = w1 + t*CC;
        for(int c=0;c<CC;c++) s += av[c]*wr[c];
        hid[t] = fmaxf(s, 0.f);
    }
    __syncthreads();
    for(int j=t;j<NB*CC;j+=256){
        float s = b2[j];
        const float* wr = w2 + j*HID;
        #pragma unroll
        for(int i=0;i<HID;i++) s += hid[i]*wr[i];
        g_cw[b*NB*CC + j] = 1.f/(1.f + expf(-s));
    }
}

// ---------------- masks -> circular-conv kernels -------------------------
__device__ __forceinline__ double dsig(float a){ return 1.0/(1.0 + exp(-(double)a)); }

__global__ void k_mker(const float* __restrict__ lcp, const float* __restrict__ hcp){
    __shared__ float msk[NB*NP];
    __shared__ double ct[16];
    int t = threadIdx.x;
    if(t < 16) ct[t] = cos(6.283185307179586 * (double)t / 16.0);
    float lc = *lcp, hc = *hcp;
    {
        int i = t>>4, j = t&15;
        const float step = 0.13333334f;
        float yy = __fadd_rn(-1.0f, __fmul_rn((float)i, step));
        float xx = __fadd_rn(-1.0f, __fmul_rn((float)j, step));
        float d2 = __fadd_rn(__fmul_rn(xx,xx), __fmul_rn(yy,yy));
        float dist = __fdiv_rn(__fsqrt_rn(d2), 1.41421356f);
        float a_l  = __fdiv_rn(__fsub_rn(lc, dist), 1e-6f);
        float a_m1 = __fdiv_rn(__fsub_rn(dist, lc), 1e-6f);
        float a_m2 = __fdiv_rn(__fsub_rn(hc, dist), 1e-6f);
        float a_h  = __fdiv_rn(__fsub_rn(dist, hc), 1e-6f);
        msk[0*NP + t] = (float)dsig(a_l);
        msk[1*NP + t] = (float)(dsig(a_m1)*dsig(a_m2));
        msk[2*NP + t] = (float)dsig(a_h);
    }
    __syncthreads();
    int ph = t>>4, pw = t&15;
    for(int s=0;s<NB;s++){
        double acc = 0.0;
        for(int u=0;u<16;u++)
            for(int v=0;v<16;v++){
                float mv = msk[s*NP + ((((u+8)&15)<<4) | ((v+8)&15))];
                acc += (double)mv * ct[(u*ph + v*pw)&15];
            }
        g_mker[s*NP + t] = (float)(acc/256.0);
    }
}

// ---------------- transpose x to [b][p][c] -------------------------------
__global__ void k_xt(const float* __restrict__ x){
    __shared__ float sm[32][33];
    int b = blockIdx.z, c0 = blockIdx.y*32, p0 = blockIdx.x*32;
    int tx = threadIdx.x, ty = threadIdx.y;
    sm[ty][tx] = x[((size_t)b*CC + c0+ty)*NP + p0+tx];
    __syncthreads();
    g_xT[((size_t)b*NP + p0+ty)*CC + c0+tx] = sm[tx][ty];
}

// ---------------- weights -> [s][hi/lo][o][tap*320+c] bf16 ---------------
__global__ void k_wb(const float* __restrict__ lw, const float* __restrict__ mw,
                     const float* __restrict__ hw){
    size_t idx = (size_t)blockIdx.x*256 + threadIdx.x;
    const size_t tot = (size_t)NB*2*CC*KTOT;
    if(idx >= tot) return;
    int k = (int)(idx % KTOT);
    int o = (int)((idx/KTOT) % CC);
    int v = (int)((idx/((size_t)KTOT*CC)) % 2);
    int s = (int)(idx/((size_t)KTOT*CC*2));
    int tap = k/320, c = k%320;
    const float* w = (s==0)?lw:((s==1)?mw:hw);
    float val = w[(size_t)o*KTOT + (size_t)c*9 + tap];
    __nv_bfloat16 h = __float2bfloat16(val);
    g_wb[idx] = (v==0) ? h : __float2bfloat16(val - __bfloat162float(h));
}

// ---------------- zero padded borders (both hi/lo) -----------------------
__global__ void k_zero(){
    int idx = blockIdx.x*256 + threadIdx.x;
    const int per = NB*BB*68*40;
    if(idx >= 2*per) return;
    int buf = idx/per, rem = idx%per;
    int q  = rem % 40;
    int bi = (rem/40) % 68;
    int pl = rem/(40*68);
    int r, cn;
    if(bi < 18){ r = 0;  cn = bi; }
    else if(bi < 36){ r = 17; cn = bi-18; }
    else { int k = bi-36; r = 1 + (k>>1); cn = (k&1) ? 17 : 0; }
    uint4* base = buf ? (uint4*)g_bplo : (uint4*)g_bphi;
    base[ (((size_t)pl*18 + r)*18 + cn)*40 + q ] = make_uint4(0u,0u,0u,0u);
}

// ---------------- band filter -> bf16 hi/lo padded planes ----------------
__device__ __forceinline__ void store16_hl(__nv_bfloat16* dh, __nv_bfloat16* dl,
                                           const float* a){
    #pragma unroll
    for(int j=0;j<8;j++){
        float v0 = a[2*j], v1 = a[2*j+1];
        __nv_bfloat16 h0 = __float2bfloat16(v0), h1 = __float2bfloat16(v1);
        ((__nv_bfloat162*)dh)[j] = __nv_bfloat162(h0, h1);
        ((__nv_bfloat162*)dl)[j] = __nv_bfloat162(
            __float2bfloat16(v0 - __bfloat162float(h0)),
            __float2bfloat16(v1 - __bfloat162float(h1)));
    }
}

__global__ void __launch_bounds__(256) k_band(const float* __restrict__ x){
    __shared__ float Xs[NP][36];
    __shared__ float ms[NB*NP];
    int b = blockIdx.y, c0 = blockIdx.x*32, t = threadIdx.x;
    for(int i=t;i<NB*NP;i+=256) ms[i] = g_mker[i];
    const float* xb = x + ((size_t)b*CC + c0)*NP;
    for(int i=t;i<2048;i+=256){
        int cl = i>>6, q4 = (i&63)<<2;
        float4 v = *(const float4*)(xb + (size_t)cl*NP + q4);
        Xs[q4+0][cl]=v.x; Xs[q4+1][cl]=v.y; Xs[q4+2][cl]=v.z; Xs[q4+3][cl]=v.w;
    }
    __syncthreads();
    int cg = t&1, pg = t>>1;
    int pA = pg*2, pB = pg*2+1;
    int phA = pA>>4, pwA = pA&15, phB = pB>>4, pwB = pB&15;
    for(int s=0;s<NB;s++){
        const float* msp = ms + s*NP;
        float a0[16], a1[16];
        #pragma unroll
        for(int j=0;j<16;j++){ a0[j]=0.f; a1[j]=0.f; }
        for(int q=0;q<NP;q++){
            int qh=q>>4, qw=q&15;
            float m0 = msp[(((phA-qh)&15)<<4) | ((pwA-qw)&15)];
            float m1 = msp[(((phB-qh)&15)<<4) | ((pwB-qw)&15)];
            const float* xr = &Xs[q][cg*16];
            float4 v0 = *(const float4*)(xr+0);
            float4 v1 = *(const float4*)(xr+4);
            float4 v2 = *(const float4*)(xr+8);
            float4 v3 = *(const float4*)(xr+12);
            a0[0]+=m0*v0.x; a0[1]+=m0*v0.y; a0[2]+=m0*v0.z; a0[3]+=m0*v0.w;
            a0[4]+=m0*v1.x; a0[5]+=m0*v1.y; a0[6]+=m0*v1.z; a0[7]+=m0*v1.w;
            a0[8]+=m0*v2.x; a0[9]+=m0*v2.y; a0[10]+=m0*v2.z; a0[11]+=m0*v2.w;
            a0[12]+=m0*v3.x; a0[13]+=m0*v3.y; a0[14]+=m0*v3.z; a0[15]+=m0*v3.w;
            a1[0]+=m1*v0.x; a1[1]+=m1*v0.y; a1[2]+=m1*v0.z; a1[3]+=m1*v0.w;
            a1[4]+=m1*v1.x; a1[5]+=m1*v1.y; a1[6]+=m1*v1.z; a1[7]+=m1*v1.w;
            a1[8]+=m1*v2.x; a1[9]+=m1*v2.y; a1[10]+=m1*v2.z; a1[11]+=m1*v2.w;
            a1[12]+=m1*v3.x; a1[13]+=m1*v3.y; a1[14]+=m1*v3.z; a1[15]+=m1*v3.w;
        }
        {
            size_t off = ((((size_t)(s*BB+b)*18 + phA+1)*18) + pwA+1)*CC + c0 + cg*16;
            store16_hl(g_bphi+off, g_bplo+off, a0);
        }
        {
            size_t off = ((((size_t)(s*BB+b)*18 + phB+1)*18) + pwB+1)*CC + c0 + cg*16;
            store16_hl(g_bphi+off, g_bplo+off, a1);
        }
    }
}

// ---------------- 3x3 conv via bf16-split mma.sync GEMM ------------------
__global__ void __launch_bounds__(256) k_conv_mma(const float* __restrict__ lb,
                                                  const float* __restrict__ mb,
                                                  const float* __restrict__ hb){
    extern __shared__ char smem[];
    uint32_t sb = smem_u32(smem);
    int t = threadIdx.x, wid = t>>5, lane = t&31;
    int s = blockIdx.z, b = blockIdx.y;
    int p0 = (blockIdx.x & 1)*128;
    int n0 = (blockIdx.x >> 1)*160;
    int wm = wid>>2, wn = wid&3;           // warp tile: rows wm*64, cols wn*40

    const __nv_bfloat16* ahi = g_bphi + (size_t)(s*BB+b)*18*18*CC;
    const __nv_bfloat16* alo = g_bplo + (size_t)(s*BB+b)*18*18*CC;
    const __nv_bfloat16* whi = g_wb + (size_t)(s*2+0)*CC*KTOT;
    const __nv_bfloat16* wlo = g_wb + (size_t)(s*2+1)*CC*KTOT;

    float acc[4][5][4];
    #pragma unroll
    for(int i=0;i<4;i++)
        #pragma unroll
        for(int j=0;j<5;j++){ acc[i][j][0]=0.f; acc[i][j][1]=0.f; acc[i][j][2]=0.f; acc[i][j][3]=0.f; }

    auto issue_loads = [&](int ci, int st){
        int split = ci/45;
        int tap   = (ci%45)/5;
        int kc    = (ci%5)*64;
        int dy = tap/3, dx = tap%3;
        const __nv_bfloat16* ab = (split==2) ? alo : ahi;
        const __nv_bfloat16* wb = (split==1) ? wlo : whi;
        uint32_t offA = sb + st*STAGE;
        uint32_t offB = sb + st*STAGE + ASTAGE;
        #pragma unroll
        for(int i=0;i<4;i++){
            int lin = i*256 + t;
            int r = lin>>3, m = lin&7;
            int p = p0 + r;
            int h = (p>>4)+dy, w = (p&15)+dx;
            const char* src = (const char*)ab + ((size_t)(h*18+w)*CC + kc + m*8)*2;
            CP_ASYNC16(offA + SWZ(r*128 + m*16), src);
        }
        #pragma unroll
        for(int i=0;i<5;i++){
            int lin = i*256 + t;
            int o = lin>>3, m = lin&7;
            const char* src = (const char*)wb + ((size_t)(n0+o)*KTOT + tap*320 + kc + m*8)*2;
            CP_ASYNC16(offB + SWZ(o*128 + m*16), src);
        }
        CP_COMMIT();
    };

    issue_loads(0, 0);
    for(int ci=0; ci<135; ci++){
        int st = ci & 1;
        if(ci < 134) issue_loads(ci+1, st^1);
        if(ci < 134) CP_WAIT1(); else CP_WAIT0();
        __syncthreads();

        uint32_t baseA = sb + st*STAGE + (uint32_t)(wm*64)*128;
        uint32_t baseB = sb + st*STAGE + ASTAGE + (uint32_t)(wn*40)*128;
        int la = lane & 15, lb16 = (lane>>4);      // A ldmatrix addressing
        int lbr = lane & 7, lbc = (lane>>3)&1;     // B ldmatrix addressing
        #pragma unroll
        for(int kt=0; kt<4; kt++){
            uint32_t a[4][4];
            #pragma unroll
            for(int mt=0; mt<4; mt++){
                uint32_t addr = baseA + SWZ((uint32_t)(mt*16 + la)*128 + kt*32 + lb16*16);
                LDMX4(a[mt][0], a[mt][1], a[mt][2], a[mt][3], addr);
            }
            #pragma unroll
            for(int nt=0; nt<5; nt++){
                uint32_t b0, b1;
                uint32_t addr = baseB + SWZ((uint32_t)(nt*8 + lbr)*128 + kt*32 + lbc*16);
                LDMX2(b0, b1, addr);
                #pragma unroll
                for(int mt=0; mt<4; mt++){
                    MMA16816(acc[mt][nt][0], acc[mt][nt][1], acc[mt][nt][2], acc[mt][nt][3],
                             a[mt][0], a[mt][1], a[mt][2], a[mt][3], b0, b1);
                }
            }
        }
        __syncthreads();
    }

    const float* bias = (s==0)?lb:((s==1)?mb:hb);
    float* gout = g_conv + (size_t)(s*BB+b)*NP*CC;
    #pragma unroll
    for(int mt=0; mt<4; mt++){
        int row = p0 + wm*64 + mt*16 + (lane>>2);
        #pragma unroll
        for(int nt=0; nt<5; nt++){
            int col = n0 + wn*40 + nt*8 + (lane&3)*2;
            float bz0 = bias[col], bz1 = bias[col+1];
            *(float2*)(gout + (size_t)row*CC + col) =
                make_float2(acc[mt][nt][0]+bz0, acc[mt][nt][1]+bz1);
            *(float2*)(gout + (size_t)(row+8)*CC + col) =
                make_float2(acc[mt][nt][2]+bz0, acc[mt][nt][3]+bz1);
        }
    }
}

// ---------------- group-norm statistics ----------------------------------
__global__ void k_gn(){
    __shared__ float rs[8], rq[8];
    int g = blockIdx.x, b = blockIdx.y, s = blockIdx.z;
    int t = threadIdx.x;
    const float* base = g_conv + (size_t)(s*BB+b)*NP*CC + g*64;
    float sm = 0.f, sq = 0.f;
    for(int i=t;i<16384;i+=256){
        int p = i>>6, c = i&63;
        float v = base[(size_t)p*CC + c];
        sm += v; sq += v*v;
    }
    #pragma unroll
    for(int o=16;o;o>>=1){ sm += __shfl_xor_sync(0xffffffffu, sm, o);
                           sq += __shfl_xor_sync(0xffffffffu, sq, o); }
    if(!(t&31)){ rs[t>>5]=sm; rq[t>>5]=sq; }
    __syncthreads();
    if(t==0){
        float S=0.f, Q=0.f;
        for(int i=0;i<8;i++){ S+=rs[i]; Q+=rq[i]; }
        float mu = S*(1.0f/16384.0f);
        float var = Q*(1.0f/16384.0f) - mu*mu;
        int o = (s*BB+b)*GRP + g;
        g_mu[o] = mu;
        g_rs[o] = rsqrtf(var + 1e-5f);
    }
}

// ---------------- fuse pass 1 --------------------------------------------
__global__ void k_fuse1(const float* __restrict__ lg, const float* __restrict__ lbeta,
                        const float* __restrict__ mg, const float* __restrict__ mbeta,
                        const float* __restrict__ hg, const float* __restrict__ hbeta,
                        const float* __restrict__ saw){
    __shared__ float red[10];
    int p = blockIdx.x, b = blockIdx.y, c = threadIdx.x;
    int g = c>>6;
    float xv = g_xT[((size_t)b*NP+p)*CC + c];
    float fused = 0.f;
    #pragma unroll
    for(int s=0;s<NB;s++){
        const float* gam = (s==0)?lg:((s==1)?mg:hg);
        const float* bet = (s==0)?lbeta:((s==1)?mbeta:hbeta);
        float v  = g_conv[((size_t)(s*BB+b)*NP+p)*CC + c];
        float mu = g_mu[(s*BB+b)*GRP+g];
        float rr = g_rs[(s*BB+b)*GRP+g];
        float feat = (v-mu)*rr*gam[c] + bet[c] + xv;
        fused += g_cw[(size_t)b*NB*CC + s*CC + c] * feat;
    }
    g_fused[((size_t)b*NP+p)*CC + c] = fused;
    float part = fused * saw[c];
    #pragma unroll
    for(int o=16;o;o>>=1) part += __shfl_xor_sync(0xffffffffu, part, o);
    if(!(c&31)) red[c>>5] = part;
    __syncthreads();
    if(c==0){
        float S=0.f;
        for(int i=0;i<10;i++) S += red[i];
        g_swl[b*NP+p] = S;
    }
}

// ---------------- fuse pass 2 --------------------------------------------
__global__ void k_fuse2(const float* __restrict__ sab, float* __restrict__ out){
    __shared__ float sm[32][33];
    __shared__ float sws[32];
    int b = blockIdx.z, c0 = blockIdx.y*32, p0 = blockIdx.x*32;
    int tx = threadIdx.x, ty = threadIdx.y;
    sm[ty][tx] = g_fused[((size_t)b*NP + p0+ty)*CC + c0+tx];
    if(ty==0) sws[tx] = 1.f/(1.f + expf(-(g_swl[b*NP + p0+tx] + sab[0])));
    __syncthreads();
    out[((size_t)b*CC + c0+ty)*NP + p0+tx] = sm[tx][ty]*sws[tx];
}

extern "C" void kernel_launch(void* const* d_in, const int* in_sizes, int n_in,
                              void* d_out, int out_size){
    const float* x   = (const float*)d_in[0];
    const float* lcp = (const float*)d_in[1];
    const float* hcp = (const float*)d_in[2];
    const float* w1  = (const float*)d_in[3];
    const float* b1  = (const float*)d_in[4];
    const float* w2  = (const float*)d_in[5];
    const float* b2  = (const float*)d_in[6];
    const float* lw  = (const float*)d_in[7];
    const float* lb  = (const float*)d_in[8];
    const float* lg  = (const float*)d_in[9];
    const float* lbe = (const float*)d_in[10];
    const float* mw  = (const float*)d_in[11];
    const float* mb  = (const float*)d_in[12];
    const float* mg  = (const float*)d_in[13];
    const float* mbe = (const float*)d_in[14];
    const float* hw  = (const float*)d_in[15];
    const float* hb  = (const float*)d_in[16];
    const float* hg  = (const float*)d_in[17];
    const float* hbe = (const float*)d_in[18];
    const float* saw = (const float*)d_in[19];
    const float* sab = (const float*)d_in[20];
    float* out = (float*)d_out;

    cudaFuncSetAttribute(k_conv_mma, cudaFuncAttributeMaxDynamicSharedMemorySize, SMEM_CONV);

    k_avg <<<(BB*CC+7)/8, 256>>>(x);
    k_ca  <<<BB, 256>>>(w1,b1,w2,b2);
    k_mker<<<1, 256>>>(lcp,hcp);
    k_xt  <<<dim3(8,10,BB), dim3(32,32)>>>(x);
    k_wb  <<<(int)(((size_t)NB*2*CC*KTOT + 255)/256), 256>>>(lw,mw,hw);
    k_zero<<<(2*NB*BB*68*40 + 255)/256, 256>>>();
    k_band<<<dim3(10,BB), 256>>>(x);
    k_conv_mma<<<dim3(4,BB,NB), 256, SMEM_CONV>>>(lb,mb,hb);
    k_gn  <<<dim3(GRP,BB,NB), 256>>>();
    k_fuse1<<<dim3(NP,BB), 320>>>(lg,lbe,mg,mbe,hg,hbe,saw);
    k_fuse2<<<dim3(8,10,BB), dim3(32,32)>>>(sab,out);
}

// round 10
// speedup vs baseline: 1.9253x; 1.0487x over previous
#include <cuda_runtime.h>
#include <cuda_bf16.h>
#include <math.h>
#include <stdint.h>

#define BB 128
#define CC 320
#define NP 256
#define GRP 5
#define HID 40
#define NB 3
#define KTOT 2880          // 9*320

// ---------------- scratch ------------------------------------------------
static __device__ __align__(16) float g_avg[BB*CC];
static __device__ __align__(16) float g_cw[BB*NB*CC];
static __device__ __align__(16) float g_mker[NB*NP];
static __device__ __align__(16) __nv_bfloat16 g_wb[(size_t)NB*2*CC*KTOT];
static __device__ __align__(16) __nv_bfloat16 g_bphi[(size_t)NB*BB*18*18*CC];
static __device__ __align__(16) __nv_bfloat16 g_bplo[(size_t)NB*BB*18*18*CC];
static __device__ __align__(16) float g_conv[(size_t)NB*BB*NP*CC];
static __device__ float g_mu[NB*BB*GRP];
static __device__ float g_rs[NB*BB*GRP];

// ---------------- helpers ------------------------------------------------
__device__ __forceinline__ uint32_t smem_u32(const void* p){
    uint32_t a;
    asm("{ .reg .u64 t; cvta.to.shared.u64 t, %1; cvt.u32.u64 %0, t; }" : "=r"(a) : "l"(p));
    return a;
}
#define SWZ(x) ((x) ^ (((x)>>3)&0x70))

#define CP_ASYNC16(dst, src) \
    asm volatile("cp.async.cg.shared.global [%0], [%1], 16;" :: "r"(dst), "l"(src))
#define CP_COMMIT()  asm volatile("cp.async.commit_group;")
#define CP_WAIT1()   asm volatile("cp.async.wait_group 1;")
#define CP_WAIT0()   asm volatile("cp.async.wait_group 0;")

#define LDMX4(r0,r1,r2,r3,a) \
    asm volatile("ldmatrix.sync.aligned.m8n8.x4.shared.b16 {%0,%1,%2,%3}, [%4];" \
        : "=r"(r0),"=r"(r1),"=r"(r2),"=r"(r3) : "r"(a))
#define LDMX2(r0,r1,a) \
    asm volatile("ldmatrix.sync.aligned.m8n8.x2.shared.b16 {%0,%1}, [%2];" \
        : "=r"(r0),"=r"(r1) : "r"(a))
#define MMA16816(c0,c1,c2,c3,a0,a1,a2,a3,b0,b1) \
    asm volatile("mma.sync.aligned.m16n8k16.row.col.f32.bf16.bf16.f32 " \
        "{%0,%1,%2,%3}, {%4,%5,%6,%7}, {%8,%9}, {%0,%1,%2,%3};" \
        : "+f"(c0),"+f"(c1),"+f"(c2),"+f"(c3) \
        : "r"(a0),"r"(a1),"r"(a2),"r"(a3),"r"(b0),"r"(b1))

// SMEM stages for conv kernel
#define ASTAGE 16384           // 128 rows x 128B
#define BSTAGE 20480           // 160 rows x 128B
#define STAGE  (ASTAGE+BSTAGE) // 36864
#define SMEM_CONV (2*STAGE)    // 73728

// ---------------- channel means ------------------------------------------
__global__ void k_avg(const float* __restrict__ x){
    int row  = blockIdx.x*8 + (threadIdx.x>>5);
    int lane = threadIdx.x & 31;
    if(row >= BB*CC) return;
    const float* p = x + (size_t)row*NP;
    float s = 0.f;
    for(int k=lane;k<NP;k+=32) s += p[k];
    #pragma unroll
    for(int o=16;o;o>>=1) s += __shfl_xor_sync(0xffffffffu, s, o);
    if(!lane) g_avg[row] = s * (1.0f/NP);
}

// ---------------- combined: masks->kernels  +  weight split --------------
__device__ __forceinline__ double dsig(float a){ return 1.0/(1.0 + exp(-(double)a)); }

__global__ void k_comb(const float* __restrict__ lcp, const float* __restrict__ hcp,
                       const float* __restrict__ lw, const float* __restrict__ mw,
                       const float* __restrict__ hw){
    if(blockIdx.x == 0){
        __shared__ float msk[NB*NP];
        __shared__ double ct[16];
        int t = threadIdx.x;
        if(t < 16) ct[t] = cos(6.283185307179586 * (double)t / 16.0);
        float lc = *lcp, hc = *hcp;
        {
            int i = t>>4, j = t&15;
            const float step = 0.13333334f;
            float yy = __fadd_rn(-1.0f, __fmul_rn((float)i, step));
            float xx = __fadd_rn(-1.0f, __fmul_rn((float)j, step));
            float d2 = __fadd_rn(__fmul_rn(xx,xx), __fmul_rn(yy,yy));
            float dist = __fdiv_rn(__fsqrt_rn(d2), 1.41421356f);
            float a_l  = __fdiv_rn(__fsub_rn(lc, dist), 1e-6f);
            float a_m1 = __fdiv_rn(__fsub_rn(dist, lc), 1e-6f);
            float a_m2 = __fdiv_rn(__fsub_rn(hc, dist), 1e-6f);
            float a_h  = __fdiv_rn(__fsub_rn(dist, hc), 1e-6f);
            msk[0*NP + t] = (float)dsig(a_l);
            msk[1*NP + t] = (float)(dsig(a_m1)*dsig(a_m2));
            msk[2*NP + t] = (float)dsig(a_h);
        }
        __syncthreads();
        int ph = t>>4, pw = t&15;
        for(int s=0;s<NB;s++){
            double acc = 0.0;
            for(int u=0;u<16;u++)
                for(int v=0;v<16;v++){
                    float mv = msk[s*NP + ((((u+8)&15)<<4) | ((v+8)&15))];
                    acc += (double)mv * ct[(u*ph + v*pw)&15];
                }
            g_mker[s*NP + t] = (float)(acc/256.0);
        }
    } else {
        size_t idx = (size_t)(blockIdx.x-1)*256 + threadIdx.x;
        const size_t tot = (size_t)NB*2*CC*KTOT;
        if(idx >= tot) return;
        int k = (int)(idx % KTOT);
        int o = (int)((idx/KTOT) % CC);
        int v = (int)((idx/((size_t)KTOT*CC)) % 2);
        int s = (int)(idx/((size_t)KTOT*CC*2));
        int tap = k/320, c = k%320;
        const float* w = (s==0)?lw:((s==1)?mw:hw);
        float val = w[(size_t)o*KTOT + (size_t)c*9 + tap];
        __nv_bfloat16 h = __float2bfloat16(val);
        g_wb[idx] = (v==0) ? h : __float2bfloat16(val - __bfloat162float(h));
    }
}

// ---------------- band filter -> bf16 hi/lo padded planes ----------------
__device__ __forceinline__ void store16_hl(__nv_bfloat16* dh, __nv_bfloat16* dl,
                                           const float* a){
    #pragma unroll
    for(int j=0;j<8;j++){
        float v0 = a[2*j], v1 = a[2*j+1];
        __nv_bfloat16 h0 = __float2bfloat16(v0), h1 = __float2bfloat16(v1);
        ((__nv_bfloat162*)dh)[j] = __nv_bfloat162(h0, h1);
        ((__nv_bfloat162*)dl)[j] = __nv_bfloat162(
            __float2bfloat16(v0 - __bfloat162float(h0)),
            __float2bfloat16(v1 - __bfloat162float(h1)));
    }
}

__global__ void __launch_bounds__(256) k_band(const float* __restrict__ x){
    __shared__ float Xs[NP][36];
    __shared__ float ms[NB*NP];
    int b = blockIdx.y, c0 = blockIdx.x*32, t = threadIdx.x;

    // zero the padded borders for this (b, c-range), all bands, both bufs
    for(int i=t;i<1632;i+=256){
        int q   = i & 3;
        int buf = (i>>2) & 1;
        int bi  = (i>>3) % 68;
        int s   = i / (68*8);
        int r, cn;
        if(bi < 18){ r = 0;  cn = bi; }
        else if(bi < 36){ r = 17; cn = bi-18; }
        else { int kk = bi-36; r = 1 + (kk>>1); cn = (kk&1) ? 17 : 0; }
        __nv_bfloat16* base = buf ? g_bplo : g_bphi;
        *(uint4*)(base + (((size_t)(s*BB+b)*18 + r)*18 + cn)*CC + c0 + q*8) =
            make_uint4(0u,0u,0u,0u);
    }

    for(int i=t;i<NB*NP;i+=256) ms[i] = g_mker[i];
    const float* xb = x + ((size_t)b*CC + c0)*NP;
    for(int i=t;i<2048;i+=256){
        int cl = i>>6, q4 = (i&63)<<2;
        float4 v = *(const float4*)(xb + (size_t)cl*NP + q4);
        Xs[q4+0][cl]=v.x; Xs[q4+1][cl]=v.y; Xs[q4+2][cl]=v.z; Xs[q4+3][cl]=v.w;
    }
    __syncthreads();
    int cg = t&1, pg = t>>1;
    int pA = pg*2, pB = pg*2+1;
    int phA = pA>>4, pwA = pA&15, phB = pB>>4, pwB = pB&15;
    for(int s=0;s<NB;s++){
        const float* msp = ms + s*NP;
        float a0[16], a1[16];
        #pragma unroll
        for(int j=0;j<16;j++){ a0[j]=0.f; a1[j]=0.f; }
        for(int q=0;q<NP;q++){
            int qh=q>>4, qw=q&15;
            float m0 = msp[(((phA-qh)&15)<<4) | ((pwA-qw)&15)];
            float m1 = msp[(((phB-qh)&15)<<4) | ((pwB-qw)&15)];
            const float* xr = &Xs[q][cg*16];
            float4 v0 = *(const float4*)(xr+0);
            float4 v1 = *(const float4*)(xr+4);
            float4 v2 = *(const float4*)(xr+8);
            float4 v3 = *(const float4*)(xr+12);
            a0[0]+=m0*v0.x; a0[1]+=m0*v0.y; a0[2]+=m0*v0.z; a0[3]+=m0*v0.w;
            a0[4]+=m0*v1.x; a0[5]+=m0*v1.y; a0[6]+=m0*v1.z; a0[7]+=m0*v1.w;
            a0[8]+=m0*v2.x; a0[9]+=m0*v2.y; a0[10]+=m0*v2.z; a0[11]+=m0*v2.w;
            a0[12]+=m0*v3.x; a0[13]+=m0*v3.y; a0[14]+=m0*v3.z; a0[15]+=m0*v3.w;
            a1[0]+=m1*v0.x; a1[1]+=m1*v0.y; a1[2]+=m1*v0.z; a1[3]+=m1*v0.w;
            a1[4]+=m1*v1.x; a1[5]+=m1*v1.y; a1[6]+=m1*v1.z; a1[7]+=m1*v1.w;
            a1[8]+=m1*v2.x; a1[9]+=m1*v2.y; a1[10]+=m1*v2.z; a1[11]+=m1*v2.w;
            a1[12]+=m1*v3.x; a1[13]+=m1*v3.y; a1[14]+=m1*v3.z; a1[15]+=m1*v3.w;
        }
        {
            size_t off = ((((size_t)(s*BB+b)*18 + phA+1)*18) + pwA+1)*CC + c0 + cg*16;
            store16_hl(g_bphi+off, g_bplo+off, a0);
        }
        {
            size_t off = ((((size_t)(s*BB+b)*18 + phB+1)*18) + pwB+1)*CC + c0 + cg*16;
            store16_hl(g_bphi+off, g_bplo+off, a1);
        }
    }
}

// ---------------- 3x3 conv via bf16-split mma.sync GEMM ------------------
__global__ void __launch_bounds__(256) k_conv_mma(const float* __restrict__ lb,
                                                  const float* __restrict__ mb,
                                                  const float* __restrict__ hb){
    extern __shared__ char smem[];
    uint32_t sb = smem_u32(smem);
    int t = threadIdx.x, wid = t>>5, lane = t&31;
    int s = blockIdx.z, b = blockIdx.y;
    int p0 = (blockIdx.x & 1)*128;
    int n0 = (blockIdx.x >> 1)*160;
    int wm = wid>>2, wn = wid&3;           // warp tile: rows wm*64, cols wn*40

    const __nv_bfloat16* ahi = g_bphi + (size_t)(s*BB+b)*18*18*CC;
    const __nv_bfloat16* alo = g_bplo + (size_t)(s*BB+b)*18*18*CC;
    const __nv_bfloat16* whi = g_wb + (size_t)(s*2+0)*CC*KTOT;
    const __nv_bfloat16* wlo = g_wb + (size_t)(s*2+1)*CC*KTOT;

    float acc[4][5][4];
    #pragma unroll
    for(int i=0;i<4;i++)
        #pragma unroll
        for(int j=0;j<5;j++){ acc[i][j][0]=0.f; acc[i][j][1]=0.f; acc[i][j][2]=0.f; acc[i][j][3]=0.f; }

    auto issue_loads = [&](int ci, int st){
        int split = ci/45;
        int tap   = (ci%45)/5;
        int kc    = (ci%5)*64;
        int dy = tap/3, dx = tap%3;
        const __nv_bfloat16* ab = (split==2) ? alo : ahi;
        const __nv_bfloat16* wb = (split==1) ? wlo : whi;
        uint32_t offA = sb + st*STAGE;
        uint32_t offB = sb + st*STAGE + ASTAGE;
        #pragma unroll
        for(int i=0;i<4;i++){
            int lin = i*256 + t;
            int r = lin>>3, m = lin&7;
            int p = p0 + r;
            int h = (p>>4)+dy, w = (p&15)+dx;
            const char* src = (const char*)ab + ((size_t)(h*18+w)*CC + kc + m*8)*2;
            CP_ASYNC16(offA + SWZ(r*128 + m*16), src);
        }
        #pragma unroll
        for(int i=0;i<5;i++){
            int lin = i*256 + t;
            int o = lin>>3, m = lin&7;
            const char* src = (const char*)wb + ((size_t)(n0+o)*KTOT + tap*320 + kc + m*8)*2;
            CP_ASYNC16(offB + SWZ(o*128 + m*16), src);
        }
        CP_COMMIT();
    };

    issue_loads(0, 0);
    for(int ci=0; ci<135; ci++){
        int st = ci & 1;
        if(ci < 134) issue_loads(ci+1, st^1);
        if(ci < 134) CP_WAIT1(); else CP_WAIT0();
        __syncthreads();

        uint32_t baseA = sb + st*STAGE + (uint32_t)(wm*64)*128;
        uint32_t baseB = sb + st*STAGE + ASTAGE + (uint32_t)(wn*40)*128;
        int la = lane & 15, lb16 = (lane>>4);      // A ldmatrix addressing
        int lbr = lane & 7, lbc = (lane>>3)&1;     // B ldmatrix addressing
        #pragma unroll
        for(int kt=0; kt<4; kt++){
            uint32_t a[4][4];
            #pragma unroll
            for(int mt=0; mt<4; mt++){
                uint32_t addr = baseA + SWZ((uint32_t)(mt*16 + la)*128 + kt*32 + lb16*16);
                LDMX4(a[mt][0], a[mt][1], a[mt][2], a[mt][3], addr);
            }
            #pragma unroll
            for(int nt=0; nt<5; nt++){
                uint32_t b0, b1;
                uint32_t addr = baseB + SWZ((uint32_t)(nt*8 + lbr)*128 + kt*32 + lbc*16);
                LDMX2(b0, b1, addr);
                #pragma unroll
                for(int mt=0; mt<4; mt++){
                    MMA16816(acc[mt][nt][0], acc[mt][nt][1], acc[mt][nt][2], acc[mt][nt][3],
                             a[mt][0], a[mt][1], a[mt][2], a[mt][3], b0, b1);
                }
            }
        }
        __syncthreads();
    }

    const float* bias = (s==0)?lb:((s==1)?mb:hb);
    float* gout = g_conv + (size_t)(s*BB+b)*NP*CC;
    #pragma unroll
    for(int mt=0; mt<4; mt++){
        int row = p0 + wm*64 + mt*16 + (lane>>2);
        #pragma unroll
        for(int nt=0; nt<5; nt++){
            int col = n0 + wn*40 + nt*8 + (lane&3)*2;
            float bz0 = bias[col], bz1 = bias[col+1];
            *(float2*)(gout + (size_t)row*CC + col) =
                make_float2(acc[mt][nt][0]+bz0, acc[mt][nt][1]+bz1);
            *(float2*)(gout + (size_t)(row+8)*CC + col) =
                make_float2(acc[mt][nt][2]+bz0, acc[mt][nt][3]+bz1);
        }
    }
}

// ---------------- channel attention --------------------------------------
__global__ void k_ca(const float* __restrict__ w1, const float* __restrict__ b1,
                     const float* __restrict__ w2, const float* __restrict__ b2){
    __shared__ float av[CC];
    __shared__ float hid[HID];
    int b = blockIdx.x, t = threadIdx.x;
    for(int c=t;c<CC;c+=256) av[c] = g_avg[b*CC+c];
    __syncthreads();
    if(t < HID){
        float s = b1[t];
        const float* wr = w1 + t*CC;
        for(int c=0;c<CC;c++) s += av[c]*wr[c];
        hid[t] = fmaxf(s, 0.f);
    }
    __syncthreads();
    for(int j=t;j<NB*CC;j+=256){
        float s = b2[j];
        const float* wr = w2 + j*HID;
        #pragma unroll
        for(int i=0;i<HID;i++) s += hid[i]*wr[i];
        g_cw[b*NB*CC + j] = 1.f/(1.f + expf(-s));
    }
}

// ---------------- group-norm statistics ----------------------------------
__global__ void k_gn(){
    __shared__ float rs[8], rq[8];
    int g = blockIdx.x, b = blockIdx.y, s = blockIdx.z;
    int t = threadIdx.x;
    const float* base = g_conv + (size_t)(s*BB+b)*NP*CC + g*64;
    float sm = 0.f, sq = 0.f;
    for(int i=t;i<16384;i+=256){
        int p = i>>6, c = i&63;
        float v = base[(size_t)p*CC + c];
        sm += v; sq += v*v;
    }
    #pragma unroll
    for(int o=16;o;o>>=1){ sm += __shfl_xor_sync(0xffffffffu, sm, o);
                           sq += __shfl_xor_sync(0xffffffffu, sq, o); }
    if(!(t&31)){ rs[t>>5]=sm; rq[t>>5]=sq; }
    __syncthreads();
    if(t==0){
        float S=0.f, Q=0.f;
        for(int i=0;i<8;i++){ S+=rs[i]; Q+=rq[i]; }
        float mu = S*(1.0f/16384.0f);
        float var = Q*(1.0f/16384.0f) - mu*mu;
        int o = (s*BB+b)*GRP + g;
        g_mu[o] = mu;
        g_rs[o] = rsqrtf(var + 1e-5f);
    }
}

// ------- fused: GN affine + residual + cw mix + SA + transpose-out -------
__global__ void __launch_bounds__(1024) k_fuse(const float* __restrict__ x,
                        const float* __restrict__ lg, const float* __restrict__ lbeta,
                        const float* __restrict__ mg, const float* __restrict__ mbeta,
                        const float* __restrict__ hg, const float* __restrict__ hbeta,
                        const float* __restrict__ saw, const float* __restrict__ sab,
                        float* __restrict__ out){
    __shared__ float xs[CC*33];
    __shared__ float cws[NB*CC];
    int b = blockIdx.y, p0 = blockIdx.x*32;
    int t = threadIdx.x, w = t>>5, lane = t&31;

    #pragma unroll
    for(int i=0;i<10;i++){
        int idx = t + i*1024;
        int c = idx>>5, j = idx&31;
        xs[c*33+j] = x[((size_t)b*CC+c)*NP + p0 + j];
    }
    for(int i=t;i<NB*CC;i+=1024) cws[i] = g_cw[b*NB*CC + i];
    __syncthreads();

    int p = p0 + w;
    const float* gams[NB] = {lg, mg, hg};
    const float* bets[NB] = {lbeta, mbeta, hbeta};
    float fused[10];
    float part = 0.f;
    #pragma unroll
    for(int k=0;k<10;k++){
        int c = lane + 32*k;
        float xv = xs[c*33 + w];
        float f = 0.f;
        #pragma unroll
        for(int s=0;s<NB;s++){
            float v  = g_conv[((size_t)(s*BB+b)*NP+p)*CC + c];
            int o = (s*BB+b)*GRP + (c>>6);
            float feat = (v - g_mu[o])*g_rs[o]*gams[s][c] + bets[s][c] + xv;
            f += cws[s*CC + c] * feat;
        }
        fused[k] = f;
        part += f * saw[c];
    }
    #pragma unroll
    for(int o=16;o;o>>=1) part += __shfl_xor_sync(0xffffffffu, part, o);
    float sw = 1.f/(1.f + expf(-(part + sab[0])));
    #pragma unroll
    for(int k=0;k<10;k++){
        int c = lane + 32*k;
        xs[c*33 + w] = fused[k]*sw;
    }
    __syncthreads();
    #pragma unroll
    for(int i=0;i<10;i++){
        int idx = t + i*1024;
        int c = idx>>5, j = idx&31;
        out[((size_t)b*CC+c)*NP + p0 + j] = xs[c*33+j];
    }
}

extern "C" void kernel_launch(void* const* d_in, const int* in_sizes, int n_in,
                              void* d_out, int out_size){
    const float* x   = (const float*)d_in[0];
    const float* lcp = (const float*)d_in[1];
    const float* hcp = (const float*)d_in[2];
    const float* w1  = (const float*)d_in[3];
    const float* b1  = (const float*)d_in[4];
    const float* w2  = (const float*)d_in[5];
    const float* b2  = (const float*)d_in[6];
    const float* lw  = (const float*)d_in[7];
    const float* lb  = (const float*)d_in[8];
    const float* lg  = (const float*)d_in[9];
    const float* lbe = (const float*)d_in[10];
    const float* mw  = (const float*)d_in[11];
    const float* mb  = (const float*)d_in[12];
    const float* mg  = (const float*)d_in[13];
    const float* mbe = (const float*)d_in[14];
    const float* hw  = (const float*)d_in[15];
    const float* hb  = (const float*)d_in[16];
    const float* hg  = (const float*)d_in[17];
    const float* hbe = (const float*)d_in[18];
    const float* saw = (const float*)d_in[19];
    const float* sab = (const float*)d_in[20];
    float* out = (float*)d_out;

    cudaFuncSetAttribute(k_conv_mma, cudaFuncAttributeMaxDynamicSharedMemorySize, SMEM_CONV);

    int wb_blocks = (int)(((size_t)NB*2*CC*KTOT + 255)/256);
    k_avg <<<(BB*CC+7)/8, 256>>>(x);
    k_comb<<<1+wb_blocks, 256>>>(lcp,hcp,lw,mw,hw);
    k_band<<<dim3(10,BB), 256>>>(x);
    k_conv_mma<<<dim3(4,BB,NB), 256, SMEM_CONV>>>(lb,mb,hb);
    k_ca  <<<BB, 256>>>(w1,b1,w2,b2);
    k_gn  <<<dim3(GRP,BB,NB), 256>>>();
    k_fuse<<<dim3(8,BB), 1024>>>(x,lg,lbe,mg,mbe,hg,hbe,saw,sab,out);
}

// round 11
// speedup vs baseline: 2.2789x; 1.1837x over previous
#include <cuda_runtime.h>
#include <cuda_bf16.h>
#include <math.h>
#include <stdint.h>

#define BB 128
#define CC 320
#define NP 256
#define GRP 5
#define HID 40
#define NB 3
#define KTOT 2880          // 9*320

// ---------------- scratch ------------------------------------------------
static __device__ __align__(16) float g_avg[BB*CC];
static __device__ __align__(16) float g_cw[BB*NB*CC];
static __device__ __align__(16) float g_mker[NB*NP];
static __device__ __align__(16) __nv_bfloat16 g_xh[(size_t)BB*CC*NP];
static __device__ __align__(16) __nv_bfloat16 g_xl[(size_t)BB*CC*NP];
static __device__ __align__(16) __nv_bfloat16 g_tm[(size_t)NB*2*NP*NP];
static __device__ __align__(16) __nv_bfloat16 g_wb[(size_t)NB*2*CC*KTOT];
static __device__ __align__(16) __nv_bfloat16 g_bphi[(size_t)NB*BB*18*18*CC];
static __device__ __align__(16) __nv_bfloat16 g_bplo[(size_t)NB*BB*18*18*CC];
static __device__ __align__(16) float g_conv[(size_t)NB*BB*NP*CC];
static __device__ float g_mu[NB*BB*GRP];
static __device__ float g_rs[NB*BB*GRP];

// ---------------- helpers ------------------------------------------------
__device__ __forceinline__ uint32_t smem_u32(const void* p){
    uint32_t a;
    asm("{ .reg .u64 t; cvta.to.shared.u64 t, %1; cvt.u32.u64 %0, t; }" : "=r"(a) : "l"(p));
    return a;
}
#define SWZ(x) ((x) ^ (((x)>>3)&0x70))

#define CP_ASYNC16(dst, src) \
    asm volatile("cp.async.cg.shared.global [%0], [%1], 16;" :: "r"(dst), "l"(src))
#define CP_COMMIT()  asm volatile("cp.async.commit_group;")
#define CP_WAIT1()   asm volatile("cp.async.wait_group 1;")
#define CP_WAIT0()   asm volatile("cp.async.wait_group 0;")

#define LDMX4(r0,r1,r2,r3,a) \
    asm volatile("ldmatrix.sync.aligned.m8n8.x4.shared.b16 {%0,%1,%2,%3}, [%4];" \
        : "=r"(r0),"=r"(r1),"=r"(r2),"=r"(r3) : "r"(a))
#define LDMX2(r0,r1,a) \
    asm volatile("ldmatrix.sync.aligned.m8n8.x2.shared.b16 {%0,%1}, [%2];" \
        : "=r"(r0),"=r"(r1) : "r"(a))
#define MMA16816(c0,c1,c2,c3,a0,a1,a2,a3,b0,b1) \
    asm volatile("mma.sync.aligned.m16n8k16.row.col.f32.bf16.bf16.f32 " \
        "{%0,%1,%2,%3}, {%4,%5,%6,%7}, {%8,%9}, {%0,%1,%2,%3};" \
        : "+f"(c0),"+f"(c1),"+f"(c2),"+f"(c3) \
        : "r"(a0),"r"(a1),"r"(a2),"r"(a3),"r"(b0),"r"(b1))

// SMEM stages
#define ASTAGE 16384           // conv: A 128 rows x 128B
#define BSTAGE 20480           // conv: B 160 rows x 128B
#define STAGE  (ASTAGE+BSTAGE) // 36864
#define SMEM_CONV (2*STAGE)    // 73728
#define BSTG 24576             // band: A 8KB + B 16KB
#define SMEM_BAND (2*BSTG)     // 49152

// ---------------- channel means + x -> bf16 hi/lo ------------------------
__global__ void k_avg(const float* __restrict__ x){
    int row  = blockIdx.x*8 + (threadIdx.x>>5);
    int lane = threadIdx.x & 31;
    if(row >= BB*CC) return;
    const float* p = x + (size_t)row*NP;
    float s = 0.f;
    #pragma unroll
    for(int j=0;j<8;j++){
        int k = j*32 + lane;
        float v = p[k];
        s += v;
        __nv_bfloat16 h = __float2bfloat16(v);
        g_xh[(size_t)row*NP + k] = h;
        g_xl[(size_t)row*NP + k] = __float2bfloat16(v - __bfloat162float(h));
    }
    #pragma unroll
    for(int o=16;o;o>>=1) s += __shfl_xor_sync(0xffffffffu, s, o);
    if(!lane) g_avg[row] = s * (1.0f/NP);
}

// ---------------- combined: masks->kernels  +  weight split --------------
__device__ __forceinline__ double dsig(float a){ return 1.0/(1.0 + exp(-(double)a)); }

__global__ void k_comb(const float* __restrict__ lcp, const float* __restrict__ hcp,
                       const float* __restrict__ lw, const float* __restrict__ mw,
                       const float* __restrict__ hw){
    if(blockIdx.x == 0){
        __shared__ float msk[NB*NP];
        __shared__ double ct[16];
        int t = threadIdx.x;
        if(t < 16) ct[t] = cos(6.283185307179586 * (double)t / 16.0);
        float lc = *lcp, hc = *hcp;
        {
            int i = t>>4, j = t&15;
            const float step = 0.13333334f;
            float yy = __fadd_rn(-1.0f, __fmul_rn((float)i, step));
            float xx = __fadd_rn(-1.0f, __fmul_rn((float)j, step));
            float d2 = __fadd_rn(__fmul_rn(xx,xx), __fmul_rn(yy,yy));
            float dist = __fdiv_rn(__fsqrt_rn(d2), 1.41421356f);
            float a_l  = __fdiv_rn(__fsub_rn(lc, dist), 1e-6f);
            float a_m1 = __fdiv_rn(__fsub_rn(dist, lc), 1e-6f);
            float a_m2 = __fdiv_rn(__fsub_rn(hc, dist), 1e-6f);
            float a_h  = __fdiv_rn(__fsub_rn(dist, hc), 1e-6f);
            msk[0*NP + t] = (float)dsig(a_l);
            msk[1*NP + t] = (float)(dsig(a_m1)*dsig(a_m2));
            msk[2*NP + t] = (float)dsig(a_h);
        }
        __syncthreads();
        int ph = t>>4, pw = t&15;
        for(int s=0;s<NB;s++){
            double acc = 0.0;
            for(int u=0;u<16;u++)
                for(int v=0;v<16;v++){
                    float mv = msk[s*NP + ((((u+8)&15)<<4) | ((v+8)&15))];
                    acc += (double)mv * ct[(u*ph + v*pw)&15];
                }
            g_mker[s*NP + t] = (float)(acc/256.0);
        }
    } else {
        size_t idx = (size_t)(blockIdx.x-1)*256 + threadIdx.x;
        const size_t tot = (size_t)NB*2*CC*KTOT;
        if(idx >= tot) return;
        int k = (int)(idx % KTOT);
        int o = (int)((idx/KTOT) % CC);
        int v = (int)((idx/((size_t)KTOT*CC)) % 2);
        int s = (int)(idx/((size_t)KTOT*CC*2));
        int tap = k/320, c = k%320;
        const float* w = (s==0)?lw:((s==1)?mw:hw);
        float val = w[(size_t)o*KTOT + (size_t)c*9 + tap];
        __nv_bfloat16 h = __float2bfloat16(val);
        g_wb[idx] = (v==0) ? h : __float2bfloat16(val - __bfloat162float(h));
    }
}

// ---------------- circulant band matrices T_s[p][q] (bf16 hi/lo) ---------
__global__ void k_tmat(){
    int idx = blockIdx.x*256 + threadIdx.x;   // < 196608
    int s   = idx >> 16;
    int rem = idx & 65535;
    int p = rem >> 8, q = rem & 255;
    int ph=p>>4, pw=p&15, qh=q>>4, qw=q&15;
    float mv = g_mker[s*NP + ((((ph-qh)&15)<<4) | ((pw-qw)&15))];
    __nv_bfloat16 h = __float2bfloat16(mv);
    g_tm[(size_t)(s*2+0)*65536 + rem] = h;
    g_tm[(size_t)(s*2+1)*65536 + rem] = __float2bfloat16(mv - __bfloat162float(h));
}

// ---------------- band filter via bf16-split mma GEMM --------------------
// out[c][p] = sum_q x[c][q] * T_s[p][q]; writes interior of padded planes.
// Borders of g_bphi/g_bplo are never written => stay zero (zero-init).
__global__ void __launch_bounds__(256, 2) k_bandmma(){
    extern __shared__ char smem[];
    uint32_t sb = smem_u32(smem);
    int t = threadIdx.x, wid = t>>5, lane = t&31;
    int s = blockIdx.z, b = blockIdx.y;
    int pt = blockIdx.x/5, ct = blockIdx.x%5;
    int p0 = pt*128, c0 = ct*64;
    int wm = wid>>2, wn = wid&3;           // 2 x 4 warps

    float acc[2][4][4];
    #pragma unroll
    for(int i=0;i<2;i++)
        #pragma unroll
        for(int j=0;j<4;j++){ acc[i][j][0]=0.f; acc[i][j][1]=0.f; acc[i][j][2]=0.f; acc[i][j][3]=0.f; }

    auto issue = [&](int ci, int st){
        int v = ci>>2, kc = (ci&3)*64;
        const __nv_bfloat16* xa = (v==2) ? g_xl : g_xh;
        const __nv_bfloat16* tb = g_tm + (size_t)(s*2 + (v==1 ? 1 : 0))*65536;
        uint32_t offA = sb + st*BSTG;
        uint32_t offB = offA + 8192;
        #pragma unroll
        for(int i=0;i<2;i++){
            int lin = i*256 + t;
            int r = lin>>3, m = lin&7;
            const char* src = (const char*)(xa + ((size_t)(b*CC + c0 + r)*NP + kc + m*8));
            CP_ASYNC16(offA + SWZ(r*128 + m*16), src);
        }
        #pragma unroll
        for(int i=0;i<4;i++){
            int lin = i*256 + t;
            int o = lin>>3, m = lin&7;
            const char* src = (const char*)(tb + ((size_t)(p0 + o)*NP + kc + m*8));
            CP_ASYNC16(offB + SWZ(o*128 + m*16), src);
        }
        CP_COMMIT();
    };

    issue(0, 0);
    for(int ci=0; ci<12; ci++){
        int st = ci & 1;
        if(ci < 11) issue(ci+1, st^1);
        if(ci < 11) CP_WAIT1(); else CP_WAIT0();
        __syncthreads();

        uint32_t baseA = sb + st*BSTG + (uint32_t)(wm*32)*128;
        uint32_t baseB = sb + st*BSTG + 8192 + (uint32_t)(wn*32)*128;
        int la = lane & 15, lb16 = lane>>4;
        int lbr = lane & 7, lbc = (lane>>3)&1;
        #pragma unroll
        for(int kt=0; kt<4; kt++){
            uint32_t a[2][4];
            #pragma unroll
            for(int mt=0; mt<2; mt++){
                uint32_t addr = baseA + SWZ((uint32_t)(mt*16 + la)*128 + kt*32 + lb16*16);
                LDMX4(a[mt][0], a[mt][1], a[mt][2], a[mt][3], addr);
            }
            #pragma unroll
            for(int nt=0; nt<4; nt++){
                uint32_t b0, b1;
                uint32_t addr = baseB + SWZ((uint32_t)(nt*8 + lbr)*128 + kt*32 + lbc*16);
                LDMX2(b0, b1, addr);
                #pragma unroll
                for(int mt=0; mt<2; mt++){
                    MMA16816(acc[mt][nt][0], acc[mt][nt][1], acc[mt][nt][2], acc[mt][nt][3],
                             a[mt][0], a[mt][1], a[mt][2], a[mt][3], b0, b1);
                }
            }
        }
        __syncthreads();
    }

    // epilogue: stage acc in smem, transpose, emit bf16 hi/lo planes
    float* ts = (float*)smem;      // [64][131]
    #pragma unroll
    for(int mt=0; mt<2; mt++){
        int row = wm*32 + mt*16 + (lane>>2);
        #pragma unroll
        for(int nt=0; nt<4; nt++){
            int col = wn*32 + nt*8 + (lane&3)*2;
            ts[row*131 + col]       = acc[mt][nt][0];
            ts[row*131 + col+1]     = acc[mt][nt][1];
            ts[(row+8)*131 + col]   = acc[mt][nt][2];
            ts[(row+8)*131 + col+1] = acc[mt][nt][3];
        }
    }
    __syncthreads();
    {
        int pl = t & 127, cb = (t>>7)*32;
        int p = p0 + pl, h = p>>4, w = p&15;
        size_t off = (((size_t)(s*BB+b)*18 + h+1)*18 + (w+1))*CC + c0 + cb;
        #pragma unroll
        for(int j=0;j<16;j++){
            float v0 = ts[(cb+2*j)*131 + pl];
            float v1 = ts[(cb+2*j+1)*131 + pl];
            __nv_bfloat16 h0 = __float2bfloat16(v0), h1 = __float2bfloat16(v1);
            ((__nv_bfloat162*)(g_bphi+off))[j] = __nv_bfloat162(h0, h1);
            ((__nv_bfloat162*)(g_bplo+off))[j] = __nv_bfloat162(
                __float2bfloat16(v0 - __bfloat162float(h0)),
                __float2bfloat16(v1 - __bfloat162float(h1)));
        }
    }
}

// ---------------- 3x3 conv via bf16-split mma.sync GEMM ------------------
__global__ void __launch_bounds__(256, 2) k_conv_mma(const float* __restrict__ lb,
                                                     const float* __restrict__ mb,
                                                     const float* __restrict__ hb){
    extern __shared__ char smem[];
    uint32_t sb = smem_u32(smem);
    int t = threadIdx.x, wid = t>>5, lane = t&31;
    int s = blockIdx.z, b = blockIdx.y;
    int p0 = (blockIdx.x & 1)*128;
    int n0 = (blockIdx.x >> 1)*160;
    int wm = wid>>2, wn = wid&3;           // warp tile: rows wm*64, cols wn*40

    const __nv_bfloat16* ahi = g_bphi + (size_t)(s*BB+b)*18*18*CC;
    const __nv_bfloat16* alo = g_bplo + (size_t)(s*BB+b)*18*18*CC;
    const __nv_bfloat16* whi = g_wb + (size_t)(s*2+0)*CC*KTOT;
    const __nv_bfloat16* wlo = g_wb + (size_t)(s*2+1)*CC*KTOT;

    float acc[4][5][4];
    #pragma unroll
    for(int i=0;i<4;i++)
        #pragma unroll
        for(int j=0;j<5;j++){ acc[i][j][0]=0.f; acc[i][j][1]=0.f; acc[i][j][2]=0.f; acc[i][j][3]=0.f; }

    auto issue_loads = [&](int ci, int st){
        int split = ci/45;
        int tap   = (ci%45)/5;
        int kc    = (ci%5)*64;
        int dy = tap/3, dx = tap%3;
        const __nv_bfloat16* ab = (split==2) ? alo : ahi;
        const __nv_bfloat16* wb = (split==1) ? wlo : whi;
        uint32_t offA = sb + st*STAGE;
        uint32_t offB = sb + st*STAGE + ASTAGE;
        #pragma unroll
        for(int i=0;i<4;i++){
            int lin = i*256 + t;
            int r = lin>>3, m = lin&7;
            int p = p0 + r;
            int h = (p>>4)+dy, w = (p&15)+dx;
            const char* src = (const char*)ab + ((size_t)(h*18+w)*CC + kc + m*8)*2;
            CP_ASYNC16(offA + SWZ(r*128 + m*16), src);
        }
        #pragma unroll
        for(int i=0;i<5;i++){
            int lin = i*256 + t;
            int o = lin>>3, m = lin&7;
            const char* src = (const char*)wb + ((size_t)(n0+o)*KTOT + tap*320 + kc + m*8)*2;
            CP_ASYNC16(offB + SWZ(o*128 + m*16), src);
        }
        CP_COMMIT();
    };

    issue_loads(0, 0);
    for(int ci=0; ci<135; ci++){
        int st = ci & 1;
        if(ci < 134) issue_loads(ci+1, st^1);
        if(ci < 134) CP_WAIT1(); else CP_WAIT0();
        __syncthreads();

        uint32_t baseA = sb + st*STAGE + (uint32_t)(wm*64)*128;
        uint32_t baseB = sb + st*STAGE + ASTAGE + (uint32_t)(wn*40)*128;
        int la = lane & 15, lb16 = (lane>>4);
        int lbr = lane & 7, lbc = (lane>>3)&1;
        #pragma unroll
        for(int kt=0; kt<4; kt++){
            uint32_t a[4][4];
            #pragma unroll
            for(int mt=0; mt<4; mt++){
                uint32_t addr = baseA + SWZ((uint32_t)(mt*16 + la)*128 + kt*32 + lb16*16);
                LDMX4(a[mt][0], a[mt][1], a[mt][2], a[mt][3], addr);
            }
            #pragma unroll
            for(int nt=0; nt<5; nt++){
                uint32_t b0, b1;
                uint32_t addr = baseB + SWZ((uint32_t)(nt*8 + lbr)*128 + kt*32 + lbc*16);
                LDMX2(b0, b1, addr);
                #pragma unroll
                for(int mt=0; mt<4; mt++){
                    MMA16816(acc[mt][nt][0], acc[mt][nt][1], acc[mt][nt][2], acc[mt][nt][3],
                             a[mt][0], a[mt][1], a[mt][2], a[mt][3], b0, b1);
                }
            }
        }
        __syncthreads();
    }

    const float* bias = (s==0)?lb:((s==1)?mb:hb);
    float* gout = g_conv + (size_t)(s*BB+b)*NP*CC;
    #pragma unroll
    for(int mt=0; mt<4; mt++){
        int row = p0 + wm*64 + mt*16 + (lane>>2);
        #pragma unroll
        for(int nt=0; nt<5; nt++){
            int col = n0 + wn*40 + nt*8 + (lane&3)*2;
            float bz0 = bias[col], bz1 = bias[col+1];
            *(float2*)(gout + (size_t)row*CC + col) =
                make_float2(acc[mt][nt][0]+bz0, acc[mt][nt][1]+bz1);
            *(float2*)(gout + (size_t)(row+8)*CC + col) =
                make_float2(acc[mt][nt][2]+bz0, acc[mt][nt][3]+bz1);
        }
    }
}

// ---------------- channel attention --------------------------------------
__global__ void k_ca(const float* __restrict__ w1, const float* __restrict__ b1,
                     const float* __restrict__ w2, const float* __restrict__ b2){
    __shared__ float av[CC];
    __shared__ float hid[HID];
    int b = blockIdx.x, t = threadIdx.x;
    for(int c=t;c<CC;c+=256) av[c] = g_avg[b*CC+c];
    __syncthreads();
    if(t < HID){
        float s = b1[t];
        const float* wr = w1 + t*CC;
        for(int c=0;c<CC;c++) s += av[c]*wr[c];
        hid[t] = fmaxf(s, 0.f);
    }
    __syncthreads();
    for(int j=t;j<NB*CC;j+=256){
        float s = b2[j];
        const float* wr = w2 + j*HID;
        #pragma unroll
        for(int i=0;i<HID;i++) s += hid[i]*wr[i];
        g_cw[b*NB*CC + j] = 1.f/(1.f + expf(-s));
    }
}

// ---------------- group-norm statistics ----------------------------------
__global__ void k_gn(){
    __shared__ float rs[8], rq[8];
    int g = blockIdx.x, b = blockIdx.y, s = blockIdx.z;
    int t = threadIdx.x;
    const float* base = g_conv + (size_t)(s*BB+b)*NP*CC + g*64;
    float sm = 0.f, sq = 0.f;
    for(int i=t;i<16384;i+=256){
        int p = i>>6, c = i&63;
        float v = base[(size_t)p*CC + c];
        sm += v; sq += v*v;
    }
    #pragma unroll
    for(int o=16;o;o>>=1){ sm += __shfl_xor_sync(0xffffffffu, sm, o);
                           sq += __shfl_xor_sync(0xffffffffu, sq, o); }
    if(!(t&31)){ rs[t>>5]=sm; rq[t>>5]=sq; }
    __syncthreads();
    if(t==0){
        float S=0.f, Q=0.f;
        for(int i=0;i<8;i++){ S+=rs[i]; Q+=rq[i]; }
        float mu = S*(1.0f/16384.0f);
        float var = Q*(1.0f/16384.0f) - mu*mu;
        int o = (s*BB+b)*GRP + g;
        g_mu[o] = mu;
        g_rs[o] = rsqrtf(var + 1e-5f);
    }
}

// ------- fused: GN affine + residual + cw mix + SA + transpose-out -------
__global__ void __launch_bounds__(1024) k_fuse(const float* __restrict__ x,
                        const float* __restrict__ lg, const float* __restrict__ lbeta,
                        const float* __restrict__ mg, const float* __restrict__ mbeta,
                        const float* __restrict__ hg, const float* __restrict__ hbeta,
                        const float* __restrict__ saw, const float* __restrict__ sab,
                        float* __restrict__ out){
    __shared__ float xs[CC*33];
    __shared__ float cws[NB*CC];
    int b = blockIdx.y, p0 = blockIdx.x*32;
    int t = threadIdx.x, w = t>>5, lane = t&31;

    #pragma unroll
    for(int i=0;i<10;i++){
        int idx = t + i*1024;
        int c = idx>>5, j = idx&31;
        xs[c*33+j] = x[((size_t)b*CC+c)*NP + p0 + j];
    }
    for(int i=t;i<NB*CC;i+=1024) cws[i] = g_cw[b*NB*CC + i];
    __syncthreads();

    int p = p0 + w;
    const float* gams[NB] = {lg, mg, hg};
    const float* bets[NB] = {lbeta, mbeta, hbeta};
    float fused[10];
    float part = 0.f;
    #pragma unroll
    for(int k=0;k<10;k++){
        int c = lane + 32*k;
        float xv = xs[c*33 + w];
        float f = 0.f;
        #pragma unroll
        for(int s=0;s<NB;s++){
            float v  = g_conv[((size_t)(s*BB+b)*NP+p)*CC + c];
            int o = (s*BB+b)*GRP + (c>>6);
            float feat = (v - g_mu[o])*g_rs[o]*gams[s][c] + bets[s][c] + xv;
            f += cws[s*CC + c] * feat;
        }
        fused[k] = f;
        part += f * saw[c];
    }
    #pragma unroll
    for(int o=16;o;o>>=1) part += __shfl_xor_sync(0xffffffffu, part, o);
    float sw = 1.f/(1.f + expf(-(part + sab[0])));
    #pragma unroll
    for(int k=0;k<10;k++){
        int c = lane + 32*k;
        xs[c*33 + w] = fused[k]*sw;
    }
    __syncthreads();
    #pragma unroll
    for(int i=0;i<10;i++){
        int idx = t + i*1024;
        int c = idx>>5, j = idx&31;
        out[((size_t)b*CC+c)*NP + p0 + j] = xs[c*33+j];
    }
}

extern "C" void kernel_launch(void* const* d_in, const int* in_sizes, int n_in,
                              void* d_out, int out_size){
    const float* x   = (const float*)d_in[0];
    const float* lcp = (const float*)d_in[1];
    const float* hcp = (const float*)d_in[2];
    const float* w1  = (const float*)d_in[3];
    const float* b1  = (const float*)d_in[4];
    const float* w2  = (const float*)d_in[5];
    const float* b2  = (const float*)d_in[6];
    const float* lw  = (const float*)d_in[7];
    const float* lb  = (const float*)d_in[8];
    const float* lg  = (const float*)d_in[9];
    const float* lbe = (const float*)d_in[10];
    const float* mw  = (const float*)d_in[11];
    const float* mb  = (const float*)d_in[12];
    const float* mg  = (const float*)d_in[13];
    const float* mbe = (const float*)d_in[14];
    const float* hw  = (const float*)d_in[15];
    const float* hb  = (const float*)d_in[16];
    const float* hg  = (const float*)d_in[17];
    const float* hbe = (const float*)d_in[18];
    const float* saw = (const float*)d_in[19];
    const float* sab = (const float*)d_in[20];
    float* out = (float*)d_out;

    cudaFuncSetAttribute(k_conv_mma, cudaFuncAttributeMaxDynamicSharedMemorySize, SMEM_CONV);
    cudaFuncSetAttribute(k_bandmma, cudaFuncAttributeMaxDynamicSharedMemorySize, SMEM_BAND);

    int wb_blocks = (int)(((size_t)NB*2*CC*KTOT + 255)/256);
    k_avg   <<<(BB*CC+7)/8, 256>>>(x);
    k_comb  <<<1+wb_blocks, 256>>>(lcp,hcp,lw,mw,hw);
    k_tmat  <<<768, 256>>>();
    k_bandmma<<<dim3(10,BB,NB), 256, SMEM_BAND>>>();
    k_conv_mma<<<dim3(4,BB,NB), 256, SMEM_CONV>>>(lb,mb,hb);
    k_ca    <<<BB, 256>>>(w1,b1,w2,b2);
    k_gn    <<<dim3(GRP,BB,NB), 256>>>();
    k_fuse  <<<dim3(8,BB), 1024>>>(x,lg,lbe,mg,mbe,hg,hbe,saw,sab,out);
}